// round 9
// baseline (speedup 1.0000x reference)
#include <cuda_runtime.h>
#include <cuda_bf16.h>
#include <math.h>

// ---------------- problem constants ----------------
#define NUM_TABLES 26
#define N_ROWS 100000
#define EMB_M 64
#define BATCH 16384
#define BAG_L 2
#define NI 27                 // 1 + NUM_TABLES
#define NPAIRS 351            // 27*26/2
#define R_W 416               // 64 + 351 = 415, padded to 416
#define TS_LD 68              // smem row pitch (floats): 16B-aligned, bank-rotating

// ---------------- scratch (static device globals; no cudaMalloc allowed) ----
__device__ float g_x1[BATCH * 512];          // bot layer0 out
__device__ float g_x2[BATCH * 256];          // bot layer1 out
__device__ float g_R [BATCH * R_W];          // [x | pairs | pad]: bot L2 writes cols 0..63
__device__ float g_z1[BATCH * 512];          // top layer0 out
__device__ float g_z2[BATCH * 256];          // top layer1 out
__device__ float g_W0p[512 * R_W];           // top_W0 repacked to stride 416 (zero pad)
__device__ int   g_idx64;                    // 1 if lS_i is int64, 0 if int32

// ---------------- index dtype detection -------------------------------------
// JAX default config silently downcasts int64 -> int32. Little-endian int64
// values < 1e5 have every odd 32-bit word == 0; int32 index data does not
// (P[64 random indices < 1e5 all zero] ~ 1e-320).
__global__ void detect_kernel(const int* __restrict__ p)
{
    if (threadIdx.x == 0) {
        int ok = 1;
        for (int i = 1; i < 128; i += 2) ok &= (p[i] == 0);
        g_idx64 = ok;
    }
}

// ---------------- bottom layer 0: [B,13] -> relu([B,512]) -------------------
__global__ __launch_bounds__(256) void bot0_kernel(
    const float* __restrict__ X, const float* __restrict__ W,
    const float* __restrict__ bias, float* __restrict__ Y)
{
    __shared__ float Ws[512 * 13];
    __shared__ float bs[512];
    __shared__ float Xs[16][13];
    int tid = threadIdx.x;
    for (int i = tid; i < 512 * 13; i += 256) Ws[i] = W[i];
    for (int i = tid; i < 512; i += 256) bs[i] = bias[i];
    int row0 = blockIdx.x * 16;
    for (int i = tid; i < 16 * 13; i += 256)
        Xs[i / 13][i % 13] = X[(long long)(row0 + i / 13) * 13 + (i % 13)];
    __syncthreads();
    for (int r = 0; r < 16; r++) {
        float xr[13];
#pragma unroll
        for (int k = 0; k < 13; k++) xr[k] = Xs[r][k];
#pragma unroll 2
        for (int c = tid; c < 512; c += 256) {
            float acc = bs[c];
#pragma unroll
            for (int k = 0; k < 13; k++) acc = fmaf(xr[k], Ws[c * 13 + k], acc);
            Y[(long long)(row0 + r) * 512 + c] = fmaxf(acc, 0.0f);
        }
    }
}

// ---------------- tf32x3 tensor-core GEMM, double-buffered ------------------
// C = act(A[M,K] @ W[N,K]^T + bias), fp32 in/out, hi/lo tf32 split for
// fp32-grade accuracy. BM=128, BK=8, BN in {64,128}, 256 threads, 2 smem
// stages; per tile: STS(next)->LDG(next+1)->compute(cur)->sync, so staging
// drains under the mma chain. SMEM swizzle col' = m ^ 8*((k&3)^((k>>2)&3)):
// conflict-free for both the STS pattern and the mma-fragment LDS pattern.

#define MMA_TF32(d, a, b0, b1)                                              \
    asm volatile("mma.sync.aligned.m16n8k8.row.col.f32.tf32.tf32.f32 "       \
        "{%0,%1,%2,%3}, {%4,%5,%6,%7}, {%8,%9}, {%0,%1,%2,%3};"              \
        : "+f"((d)[0]), "+f"((d)[1]), "+f"((d)[2]), "+f"((d)[3])             \
        : "r"((a)[0]), "r"((a)[1]), "r"((a)[2]), "r"((a)[3]),                \
          "r"(b0), "r"(b1))

template <int WIDTH>
__device__ __forceinline__ void store_split(
    unsigned (*SH)[WIDTH], unsigned (*SL)[WIDTH], int m, int kbase, float4 v)
{
    float f[4] = {v.x, v.y, v.z, v.w};
#pragma unroll
    for (int j = 0; j < 4; j++) {
        int k = kbase + j;
        int cs = (((k & 3) ^ ((k >> 2) & 3)) << 3);
        unsigned hi; asm("cvt.rna.tf32.f32 %0, %1;" : "=r"(hi) : "f"(f[j]));
        float r = f[j] - __uint_as_float(hi);
        unsigned lo; asm("cvt.rna.tf32.f32 %0, %1;" : "=r"(lo) : "f"(r));
        SH[k][m ^ cs] = hi;
        SL[k][m ^ cs] = lo;
    }
}

template <int BN, bool RELU>
__global__ __launch_bounds__(256) void gemm_tf32x3(
    const float* __restrict__ A, const float* __restrict__ W,
    const float* __restrict__ bias, float* __restrict__ C,
    int M, int N, int K, int ldc)
{
    constexpr int BM = 128, BK = 8;
    constexpr int WN  = (BN == 128) ? 2 : 1;   // warps along n
    constexpr int WM  = 8 / WN;                // warps along m
    constexpr int WTM = BM / WM;               // 32 or 16
    constexpr int WTN = BN / WN;               // 64
    constexpr int MT  = WTM / 16;              // 2 or 1
    constexpr int NT  = WTN / 8;               // 8
    constexpr int BTH = BN * 2;                // threads needed for B tile load

    __shared__ unsigned AsH[2][BK][BM], AsL[2][BK][BM];
    __shared__ unsigned BsH[2][BK][BN], BsL[2][BK][BN];

    int tid = threadIdx.x, lane = tid & 31, warp = tid >> 5;
    int wm = warp % WM, wn = warp / WM;
    int bm = blockIdx.y * BM, bn = blockIdx.x * BN;

    float acc[MT][NT][4];
#pragma unroll
    for (int i = 0; i < MT; i++)
#pragma unroll
        for (int j = 0; j < NT; j++)
#pragma unroll
            for (int t = 0; t < 4; t++) acc[i][j][t] = 0.0f;

    // tile-load mapping: one float4 per thread per operand
    int lm = tid >> 1;             // 0..127 (A rows; B rows for tid < BTH)
    int lk = (tid & 1) * 4;        // 0 or 4
    const int T_TILES = K / BK;

    const float* Ap = A + (long long)(bm + lm) * K + lk;
    const float* Wp = W + (long long)(bn + (lm & (BN - 1))) * K + lk;
    bool bload = (tid < BTH);

    // prologue: tile 0 -> stage 0, then prefetch tile 1 into regs
    float4 va = *(const float4*)Ap;
    float4 vb = bload ? *(const float4*)Wp : make_float4(0.f, 0.f, 0.f, 0.f);
    store_split<BM>(AsH[0], AsL[0], lm, lk, va);
    if (bload) store_split<BN>(BsH[0], BsL[0], lm & (BN - 1), lk, vb);
    __syncthreads();
    if (T_TILES > 1) {
        va = *(const float4*)(Ap + BK);
        if (bload) vb = *(const float4*)(Wp + BK);
    }

    for (int t = 0; t < T_TILES; t++) {
        int s = t & 1;
        // stage tile t+1 into the other buffer (drains under compute below)
        if (t + 1 < T_TILES) {
            store_split<BM>(AsH[s ^ 1], AsL[s ^ 1], lm, lk, va);
            if (bload) store_split<BN>(BsH[s ^ 1], BsL[s ^ 1], lm & (BN - 1), lk, vb);
        }
        // prefetch tile t+2
        if (t + 2 < T_TILES) {
            va = *(const float4*)(Ap + (long long)(t + 2) * BK);
            if (bload) vb = *(const float4*)(Wp + (long long)(t + 2) * BK);
        }

        // compute stage s (one 8-k-step)
        {
            int q = lane & 3, r = lane >> 2;
            int k1 = q, k2 = q + 4;
            int c1 = q << 3;            // 8*((q&3)^0)
            int c2 = (q ^ 1) << 3;      // 8*((q&3)^1)

            unsigned aH[MT][4], aL[MT][4];
#pragma unroll
            for (int mt = 0; mt < MT; mt++) {
                int m0 = wm * WTM + mt * 16 + r;
                aH[mt][0] = AsH[s][k1][m0 ^ c1];       aL[mt][0] = AsL[s][k1][m0 ^ c1];
                aH[mt][1] = AsH[s][k1][(m0 + 8) ^ c1]; aL[mt][1] = AsL[s][k1][(m0 + 8) ^ c1];
                aH[mt][2] = AsH[s][k2][m0 ^ c2];       aL[mt][2] = AsL[s][k2][m0 ^ c2];
                aH[mt][3] = AsH[s][k2][(m0 + 8) ^ c2]; aL[mt][3] = AsL[s][k2][(m0 + 8) ^ c2];
            }
#pragma unroll
            for (int nt = 0; nt < NT; nt++) {
                int n0 = wn * WTN + nt * 8 + r;
                unsigned bH0 = BsH[s][k1][n0 ^ c1], bH1 = BsH[s][k2][n0 ^ c2];
                unsigned bL0 = BsL[s][k1][n0 ^ c1], bL1 = BsL[s][k2][n0 ^ c2];
#pragma unroll
                for (int mt = 0; mt < MT; mt++) {
                    MMA_TF32(acc[mt][nt], aH[mt], bL0, bL1);
                    MMA_TF32(acc[mt][nt], aL[mt], bH0, bH1);
                    MMA_TF32(acc[mt][nt], aH[mt], bH0, bH1);
                }
            }
        }
        __syncthreads();
    }

    // epilogue
    int lane_r = lane >> 2, lane_c = (lane & 3) * 2;
#pragma unroll
    for (int mt = 0; mt < MT; mt++) {
#pragma unroll
        for (int nt = 0; nt < NT; nt++) {
            int row = bm + wm * WTM + mt * 16 + lane_r;
            int col = bn + wn * WTN + nt * 8 + lane_c;
            float bv0 = bias[col], bv1 = bias[col + 1];
            float v0 = acc[mt][nt][0] + bv0, v1 = acc[mt][nt][1] + bv1;
            float v2 = acc[mt][nt][2] + bv0, v3 = acc[mt][nt][3] + bv1;
            if (RELU) {
                v0 = fmaxf(v0, 0.0f); v1 = fmaxf(v1, 0.0f);
                v2 = fmaxf(v2, 0.0f); v3 = fmaxf(v3, 0.0f);
            }
            *(float2*)(C + (long long)row * ldc + col)       = make_float2(v0, v1);
            *(float2*)(C + (long long)(row + 8) * ldc + col) = make_float2(v2, v3);
        }
    }
}

// ---------------- fused embedding gather + dot interaction ------------------
// Two samples per 256-thread block: threads 0-127 handle sample 2*blockIdx,
// threads 128-255 handle sample 2*blockIdx+1, each against its own smem slab
// (shared only at __syncthreads). R[b, 0:64] (dense feature) was already
// written by the bottom-MLP layer-2 GEMM (ldc = R_W); this kernel gathers 26
// bags (2 rows each) from E into smem (summing the bag in-flight), reads the
// dense row into smem slot 0, and emits R[b, 64:415] = tril(T @ T^T) plus the
// zero pad at col 415. All smem traffic is float4 (pitch 68 floats).
__global__ __launch_bounds__(256) void embed_interact_kernel(
    const void* __restrict__ lS_i, const float* __restrict__ E,
    float* __restrict__ R)
{
    __shared__ float Ts2[2][NI * TS_LD];
    __shared__ int   sidx2[2][NUM_TABLES * BAG_L];
    int half = threadIdx.x >> 7;             // 0 or 1: which sample
    int tid  = threadIdx.x & 127;            // lane within the sample's 128 thr
    int b = blockIdx.x * 2 + half;
    float* Ts   = Ts2[half];
    int*   sidx = sidx2[half];
    float* Rb = R + (long long)b * R_W;

    // load 52 indices (dtype resolved at runtime)
    if (tid < NUM_TABLES * BAG_L) {
        int t = tid >> 1, w = tid & 1;
        long long base = (long long)t * (BATCH * BAG_L) + 2LL * b + w;
        sidx[tid] = g_idx64 ? (int)((const long long*)lS_i)[base]
                            : ((const int*)lS_i)[base];
    }
    // dense feature -> smem row 0 (16 float4, first 16 threads of the half)
    if (tid < EMB_M / 4)
        *(float4*)(Ts + tid * 4) = *(const float4*)(Rb + tid * 4);
    __syncthreads();

    // gather + bag-sum: 26 tables * 16 float4-chunks, coalesced within a row
#pragma unroll 2
    for (int i = tid; i < NUM_TABLES * (EMB_M / 4); i += 128) {
        int t = i >> 4, chunk = i & 15;
        long long r0 = (long long)t * N_ROWS + sidx[2 * t];
        long long r1 = (long long)t * N_ROWS + sidx[2 * t + 1];
        float4 a = ((const float4*)(E + r0 * EMB_M))[chunk];
        float4 c = ((const float4*)(E + r1 * EMB_M))[chunk];
        *(float4*)(Ts + (1 + t) * TS_LD + chunk * 4) =
            make_float4(a.x + c.x, a.y + c.y, a.z + c.z, a.w + c.w);
    }
    __syncthreads();

    if (tid == 0) Rb[R_W - 1] = 0.0f;        // zero pad column
    for (int p = tid; p < NPAIRS; p += 128) {
        int i = (int)((1.0f + sqrtf(1.0f + 8.0f * (float)p)) * 0.5f);
        while (i * (i - 1) / 2 > p) i--;
        while ((i + 1) * i / 2 <= p) i++;
        int j = p - i * (i - 1) / 2;
        const float4* ti = (const float4*)(Ts + i * TS_LD);
        const float4* tj = (const float4*)(Ts + j * TS_LD);
        float acc = 0.0f;
#pragma unroll
        for (int k = 0; k < EMB_M / 4; k++) {
            float4 u = ti[k], v = tj[k];
            acc = fmaf(u.x, v.x, acc); acc = fmaf(u.y, v.y, acc);
            acc = fmaf(u.z, v.z, acc); acc = fmaf(u.w, v.w, acc);
        }
        Rb[EMB_M + p] = acc;
    }
}

// ---------------- repack top_W0 [512,415] -> [512,416] with zero pad --------
__global__ void packw0_kernel(const float* __restrict__ W, float* __restrict__ Wp)
{
    int idx = blockIdx.x * blockDim.x + threadIdx.x;
    if (idx >= 512 * R_W) return;
    int n = idx / R_W, k = idx % R_W;
    Wp[idx] = (k < 415) ? W[(long long)n * 415 + k] : 0.0f;
}

// ---------------- top layer 2: [B,256] -> sigmoid([B,1]) --------------------
__global__ __launch_bounds__(256) void top2_kernel(
    const float* __restrict__ Z, const float* __restrict__ W,
    const float* __restrict__ bias, float* __restrict__ out)
{
    __shared__ float Wsm[256];
    int tid = threadIdx.x;
    Wsm[tid] = W[tid];
    __syncthreads();
    int warp = (blockIdx.x * blockDim.x + tid) >> 5;
    int lane = tid & 31;
    if (warp >= BATCH) return;
    const float* z = Z + (long long)warp * 256;
    float acc = 0.0f;
#pragma unroll
    for (int k = lane; k < 256; k += 32) acc = fmaf(z[k], Wsm[k], acc);
#pragma unroll
    for (int o = 16; o; o >>= 1) acc += __shfl_xor_sync(0xffffffffu, acc, o);
    if (lane == 0) out[warp] = 1.0f / (1.0f + expf(-(acc + bias[0])));
}

// ---------------- launcher --------------------------------------------------
extern "C" void kernel_launch(void* const* d_in, const int* in_sizes, int n_in,
                              void* d_out, int out_size)
{
    const float* dense_x = (const float*)d_in[0];
    // d_in[1] = lS_o (unused; uniform bags)
    const void*  lS_i    = d_in[2];
    const float* E       = (const float*)d_in[3];
    const float *bW0 = (const float*)d_in[4],  *bb0 = (const float*)d_in[5];
    const float *bW1 = (const float*)d_in[6],  *bb1 = (const float*)d_in[7];
    const float *bW2 = (const float*)d_in[8],  *bb2 = (const float*)d_in[9];
    const float *tW0 = (const float*)d_in[10], *tb0 = (const float*)d_in[11];
    const float *tW1 = (const float*)d_in[12], *tb1 = (const float*)d_in[13];
    const float *tW2 = (const float*)d_in[14], *tb2 = (const float*)d_in[15];
    float* out = (float*)d_out;

    float *x1, *x2, *R, *z1, *z2, *W0p;
    cudaGetSymbolAddress((void**)&x1,  g_x1);
    cudaGetSymbolAddress((void**)&x2,  g_x2);
    cudaGetSymbolAddress((void**)&R,   g_R);
    cudaGetSymbolAddress((void**)&z1,  g_z1);
    cudaGetSymbolAddress((void**)&z2,  g_z2);
    cudaGetSymbolAddress((void**)&W0p, g_W0p);

    // index dtype detection + weight repack (tiny)
    detect_kernel<<<1, 32>>>((const int*)lS_i);
    packw0_kernel<<<(512 * R_W + 255) / 256, 256>>>(tW0, W0p);

    // bottom MLP
    bot0_kernel<<<BATCH / 16, 256>>>(dense_x, bW0, bb0, x1);
    {
        dim3 grid(256 / 128, BATCH / 128);
        gemm_tf32x3<128, true><<<grid, 256>>>(x1, bW1, bb1, x2, BATCH, 256, 512, 256);
    }
    {   // bot layer2 writes straight into R columns 0..63 (ldc = R_W)
        dim3 grid(1, BATCH / 128);
        gemm_tf32x3<64, true><<<grid, 256>>>(x2, bW2, bb2, R, BATCH, 64, 256, R_W);
    }

    // fused embedding gather + interaction -> R cols 64..415 (2 samples/block)
    embed_interact_kernel<<<BATCH / 2, 256>>>(lS_i, E, R);

    // top MLP
    {
        dim3 grid(512 / 128, BATCH / 128);
        gemm_tf32x3<128, true><<<grid, 256>>>(R, W0p, tb0, z1, BATCH, 512, R_W, 512);
    }
    {
        dim3 grid(256 / 128, BATCH / 128);
        gemm_tf32x3<128, true><<<grid, 256>>>(z1, tW1, tb1, z2, BATCH, 256, 512, 256);
    }
    top2_kernel<<<BATCH / 8, 256>>>(z2, tW2, tb2, out);
}

// round 14
// speedup vs baseline: 1.1290x; 1.1290x over previous
#include <cuda_runtime.h>
#include <cuda_bf16.h>
#include <math.h>

// ---------------- problem constants ----------------
#define NUM_TABLES 26
#define N_ROWS 100000
#define EMB_M 64
#define BATCH 16384
#define BAG_L 2
#define NI 27                 // 1 + NUM_TABLES
#define NPAIRS 351            // 27*26/2
#define R_W 416               // 64 + 351 = 415, padded to 416
#define TS_LD 68              // smem row pitch (floats): 16B-aligned, bank-rotating

// ---------------- scratch (static device globals; no cudaMalloc allowed) ----
__device__ float g_x1[BATCH * 512];          // bot layer0 out
__device__ float g_x2[BATCH * 256];          // bot layer1 out
__device__ float g_R [BATCH * R_W];          // [x | pairs | pad]: bot L2 writes cols 0..63
__device__ float g_z1[BATCH * 512];          // top layer0 out
__device__ float g_z2[BATCH * 256];          // top layer1 out
__device__ float g_W0p[512 * R_W];           // top_W0 repacked to stride 416 (zero pad)
__device__ int   g_idx64;                    // 1 if lS_i is int64, 0 if int32

// ---------------- index dtype detection -------------------------------------
// JAX default config silently downcasts int64 -> int32. Little-endian int64
// values < 1e5 have every odd 32-bit word == 0; int32 index data does not
// (P[64 random indices < 1e5 all zero] ~ 1e-320).
__global__ void detect_kernel(const int* __restrict__ p)
{
    if (threadIdx.x == 0) {
        int ok = 1;
        for (int i = 1; i < 128; i += 2) ok &= (p[i] == 0);
        g_idx64 = ok;
    }
}

// ---------------- bottom layer 0: [B,13] -> relu([B,512]) -------------------
__global__ __launch_bounds__(256) void bot0_kernel(
    const float* __restrict__ X, const float* __restrict__ W,
    const float* __restrict__ bias, float* __restrict__ Y)
{
    __shared__ float Ws[512 * 13];
    __shared__ float bs[512];
    __shared__ float Xs[16][13];
    int tid = threadIdx.x;
    for (int i = tid; i < 512 * 13; i += 256) Ws[i] = W[i];
    for (int i = tid; i < 512; i += 256) bs[i] = bias[i];
    int row0 = blockIdx.x * 16;
    for (int i = tid; i < 16 * 13; i += 256)
        Xs[i / 13][i % 13] = X[(long long)(row0 + i / 13) * 13 + (i % 13)];
    __syncthreads();
    for (int r = 0; r < 16; r++) {
        float xr[13];
#pragma unroll
        for (int k = 0; k < 13; k++) xr[k] = Xs[r][k];
#pragma unroll 2
        for (int c = tid; c < 512; c += 256) {
            float acc = bs[c];
#pragma unroll
            for (int k = 0; k < 13; k++) acc = fmaf(xr[k], Ws[c * 13 + k], acc);
            Y[(long long)(row0 + r) * 512 + c] = fmaxf(acc, 0.0f);
        }
    }
}

// ---------------- tf32x3 tensor-core GEMM, double-buffered ------------------
// C = act(A[M,K] @ W[N,K]^T + bias), fp32 in/out, hi/lo tf32 split for
// fp32-grade accuracy. BM=128, BK=8, BN in {64,128}, 256 threads, 2 smem
// stages. __launch_bounds__(256,2) caps regs at 128 so TWO CTAs fit per SM
// (R9 ncu: regs=146 -> 1 CTA/SM, occ 12.5%, tensor 36% = latency-bound).
// SMEM swizzle col' = m ^ 8*((k&3)^((k>>2)&3)): conflict-free for both the
// STS pattern and the mma-fragment LDS pattern.

#define MMA_TF32(d, a, b0, b1)                                              \
    asm volatile("mma.sync.aligned.m16n8k8.row.col.f32.tf32.tf32.f32 "       \
        "{%0,%1,%2,%3}, {%4,%5,%6,%7}, {%8,%9}, {%0,%1,%2,%3};"              \
        : "+f"((d)[0]), "+f"((d)[1]), "+f"((d)[2]), "+f"((d)[3])             \
        : "r"((a)[0]), "r"((a)[1]), "r"((a)[2]), "r"((a)[3]),                \
          "r"(b0), "r"(b1))

template <int WIDTH>
__device__ __forceinline__ void store_split(
    unsigned (*SH)[WIDTH], unsigned (*SL)[WIDTH], int m, int kbase, float4 v)
{
    float f[4] = {v.x, v.y, v.z, v.w};
#pragma unroll
    for (int j = 0; j < 4; j++) {
        int k = kbase + j;
        int cs = (((k & 3) ^ ((k >> 2) & 3)) << 3);
        unsigned hi; asm("cvt.rna.tf32.f32 %0, %1;" : "=r"(hi) : "f"(f[j]));
        float r = f[j] - __uint_as_float(hi);
        unsigned lo; asm("cvt.rna.tf32.f32 %0, %1;" : "=r"(lo) : "f"(r));
        SH[k][m ^ cs] = hi;
        SL[k][m ^ cs] = lo;
    }
}

template <int BN, bool RELU>
__global__ __launch_bounds__(256, 2) void gemm_tf32x3(
    const float* __restrict__ A, const float* __restrict__ W,
    const float* __restrict__ bias, float* __restrict__ C,
    int M, int N, int K, int ldc)
{
    constexpr int BM = 128, BK = 8;
    constexpr int WN  = (BN == 128) ? 2 : 1;   // warps along n
    constexpr int WM  = 8 / WN;                // warps along m
    constexpr int WTM = BM / WM;               // 32 or 16
    constexpr int WTN = BN / WN;               // 64
    constexpr int MT  = WTM / 16;              // 2 or 1
    constexpr int NT  = WTN / 8;               // 8
    constexpr int BTH = BN * 2;                // threads needed for B tile load

    __shared__ unsigned AsH[2][BK][BM], AsL[2][BK][BM];
    __shared__ unsigned BsH[2][BK][BN], BsL[2][BK][BN];

    int tid = threadIdx.x, lane = tid & 31, warp = tid >> 5;
    int wm = warp % WM, wn = warp / WM;
    int bm = blockIdx.y * BM, bn = blockIdx.x * BN;

    float acc[MT][NT][4];
#pragma unroll
    for (int i = 0; i < MT; i++)
#pragma unroll
        for (int j = 0; j < NT; j++)
#pragma unroll
            for (int t = 0; t < 4; t++) acc[i][j][t] = 0.0f;

    // tile-load mapping: one float4 per thread per operand
    int lm = tid >> 1;             // 0..127 (A rows; B rows for tid < BTH)
    int lk = (tid & 1) * 4;        // 0 or 4
    const int T_TILES = K / BK;

    const float* Ap = A + (long long)(bm + lm) * K + lk;
    const float* Wp = W + (long long)(bn + (lm & (BN - 1))) * K + lk;
    bool bload = (tid < BTH);

    // prologue: tile 0 -> stage 0, then prefetch tile 1 into regs
    float4 va = *(const float4*)Ap;
    float4 vb = bload ? *(const float4*)Wp : make_float4(0.f, 0.f, 0.f, 0.f);
    store_split<BM>(AsH[0], AsL[0], lm, lk, va);
    if (bload) store_split<BN>(BsH[0], BsL[0], lm & (BN - 1), lk, vb);
    __syncthreads();
    if (T_TILES > 1) {
        va = *(const float4*)(Ap + BK);
        if (bload) vb = *(const float4*)(Wp + BK);
    }

    for (int t = 0; t < T_TILES; t++) {
        int s = t & 1;
        // stage tile t+1 into the other buffer (drains under compute below)
        if (t + 1 < T_TILES) {
            store_split<BM>(AsH[s ^ 1], AsL[s ^ 1], lm, lk, va);
            if (bload) store_split<BN>(BsH[s ^ 1], BsL[s ^ 1], lm & (BN - 1), lk, vb);
        }
        // prefetch tile t+2
        if (t + 2 < T_TILES) {
            va = *(const float4*)(Ap + (long long)(t + 2) * BK);
            if (bload) vb = *(const float4*)(Wp + (long long)(t + 2) * BK);
        }

        // compute stage s (one 8-k-step)
        {
            int q = lane & 3, r = lane >> 2;
            int k1 = q, k2 = q + 4;
            int c1 = q << 3;            // 8*((q&3)^0)
            int c2 = (q ^ 1) << 3;      // 8*((q&3)^1)

            unsigned aH[MT][4], aL[MT][4];
#pragma unroll
            for (int mt = 0; mt < MT; mt++) {
                int m0 = wm * WTM + mt * 16 + r;
                aH[mt][0] = AsH[s][k1][m0 ^ c1];       aL[mt][0] = AsL[s][k1][m0 ^ c1];
                aH[mt][1] = AsH[s][k1][(m0 + 8) ^ c1]; aL[mt][1] = AsL[s][k1][(m0 + 8) ^ c1];
                aH[mt][2] = AsH[s][k2][m0 ^ c2];       aL[mt][2] = AsL[s][k2][m0 ^ c2];
                aH[mt][3] = AsH[s][k2][(m0 + 8) ^ c2]; aL[mt][3] = AsL[s][k2][(m0 + 8) ^ c2];
            }
#pragma unroll
            for (int nt = 0; nt < NT; nt++) {
                int n0 = wn * WTN + nt * 8 + r;
                unsigned bH0 = BsH[s][k1][n0 ^ c1], bH1 = BsH[s][k2][n0 ^ c2];
                unsigned bL0 = BsL[s][k1][n0 ^ c1], bL1 = BsL[s][k2][n0 ^ c2];
#pragma unroll
                for (int mt = 0; mt < MT; mt++) {
                    MMA_TF32(acc[mt][nt], aH[mt], bL0, bL1);
                    MMA_TF32(acc[mt][nt], aL[mt], bH0, bH1);
                    MMA_TF32(acc[mt][nt], aH[mt], bH0, bH1);
                }
            }
        }
        __syncthreads();
    }

    // epilogue
    int lane_r = lane >> 2, lane_c = (lane & 3) * 2;
#pragma unroll
    for (int mt = 0; mt < MT; mt++) {
#pragma unroll
        for (int nt = 0; nt < NT; nt++) {
            int row = bm + wm * WTM + mt * 16 + lane_r;
            int col = bn + wn * WTN + nt * 8 + lane_c;
            float bv0 = __ldg(bias + col), bv1 = __ldg(bias + col + 1);
            float v0 = acc[mt][nt][0] + bv0, v1 = acc[mt][nt][1] + bv1;
            float v2 = acc[mt][nt][2] + bv0, v3 = acc[mt][nt][3] + bv1;
            if (RELU) {
                v0 = fmaxf(v0, 0.0f); v1 = fmaxf(v1, 0.0f);
                v2 = fmaxf(v2, 0.0f); v3 = fmaxf(v3, 0.0f);
            }
            *(float2*)(C + (long long)row * ldc + col)       = make_float2(v0, v1);
            *(float2*)(C + (long long)(row + 8) * ldc + col) = make_float2(v2, v3);
        }
    }
}

// ---------------- fused embedding gather + dot interaction ------------------
// Two samples per 256-thread block: threads 0-127 handle sample 2*blockIdx,
// threads 128-255 handle sample 2*blockIdx+1, each against its own smem slab
// (shared only at __syncthreads). R[b, 0:64] (dense feature) was already
// written by the bottom-MLP layer-2 GEMM (ldc = R_W); this kernel gathers 26
// bags (2 rows each) from E into smem (summing the bag in-flight), reads the
// dense row into smem slot 0, and emits R[b, 64:415] = tril(T @ T^T) plus the
// zero pad at col 415. All smem traffic is float4 (pitch 68 floats).
__global__ __launch_bounds__(256) void embed_interact_kernel(
    const void* __restrict__ lS_i, const float* __restrict__ E,
    float* __restrict__ R)
{
    __shared__ float Ts2[2][NI * TS_LD];
    __shared__ int   sidx2[2][NUM_TABLES * BAG_L];
    int half = threadIdx.x >> 7;             // 0 or 1: which sample
    int tid  = threadIdx.x & 127;            // lane within the sample's 128 thr
    int b = blockIdx.x * 2 + half;
    float* Ts   = Ts2[half];
    int*   sidx = sidx2[half];
    float* Rb = R + (long long)b * R_W;

    // load 52 indices (dtype resolved at runtime)
    if (tid < NUM_TABLES * BAG_L) {
        int t = tid >> 1, w = tid & 1;
        long long base = (long long)t * (BATCH * BAG_L) + 2LL * b + w;
        sidx[tid] = g_idx64 ? (int)((const long long*)lS_i)[base]
                            : ((const int*)lS_i)[base];
    }
    // dense feature -> smem row 0 (16 float4, first 16 threads of the half)
    if (tid < EMB_M / 4)
        *(float4*)(Ts + tid * 4) = *(const float4*)(Rb + tid * 4);
    __syncthreads();

    // gather + bag-sum: 26 tables * 16 float4-chunks, coalesced within a row
#pragma unroll 2
    for (int i = tid; i < NUM_TABLES * (EMB_M / 4); i += 128) {
        int t = i >> 4, chunk = i & 15;
        long long r0 = (long long)t * N_ROWS + sidx[2 * t];
        long long r1 = (long long)t * N_ROWS + sidx[2 * t + 1];
        float4 a = ((const float4*)(E + r0 * EMB_M))[chunk];
        float4 c = ((const float4*)(E + r1 * EMB_M))[chunk];
        *(float4*)(Ts + (1 + t) * TS_LD + chunk * 4) =
            make_float4(a.x + c.x, a.y + c.y, a.z + c.z, a.w + c.w);
    }
    __syncthreads();

    if (tid == 0) Rb[R_W - 1] = 0.0f;        // zero pad column
    for (int p = tid; p < NPAIRS; p += 128) {
        int i = (int)((1.0f + sqrtf(1.0f + 8.0f * (float)p)) * 0.5f);
        while (i * (i - 1) / 2 > p) i--;
        while ((i + 1) * i / 2 <= p) i++;
        int j = p - i * (i - 1) / 2;
        const float4* ti = (const float4*)(Ts + i * TS_LD);
        const float4* tj = (const float4*)(Ts + j * TS_LD);
        float acc = 0.0f;
#pragma unroll
        for (int k = 0; k < EMB_M / 4; k++) {
            float4 u = ti[k], v = tj[k];
            acc = fmaf(u.x, v.x, acc); acc = fmaf(u.y, v.y, acc);
            acc = fmaf(u.z, v.z, acc); acc = fmaf(u.w, v.w, acc);
        }
        Rb[EMB_M + p] = acc;
    }
}

// ---------------- repack top_W0 [512,415] -> [512,416] with zero pad --------
__global__ void packw0_kernel(const float* __restrict__ W, float* __restrict__ Wp)
{
    int idx = blockIdx.x * blockDim.x + threadIdx.x;
    if (idx >= 512 * R_W) return;
    int n = idx / R_W, k = idx % R_W;
    Wp[idx] = (k < 415) ? W[(long long)n * 415 + k] : 0.0f;
}

// ---------------- top layer 2: [B,256] -> sigmoid([B,1]) --------------------
__global__ __launch_bounds__(256) void top2_kernel(
    const float* __restrict__ Z, const float* __restrict__ W,
    const float* __restrict__ bias, float* __restrict__ out)
{
    __shared__ float Wsm[256];
    int tid = threadIdx.x;
    Wsm[tid] = W[tid];
    __syncthreads();
    int warp = (blockIdx.x * blockDim.x + tid) >> 5;
    int lane = tid & 31;
    if (warp >= BATCH) return;
    const float* z = Z + (long long)warp * 256;
    float acc = 0.0f;
#pragma unroll
    for (int k = lane; k < 256; k += 32) acc = fmaf(z[k], Wsm[k], acc);
#pragma unroll
    for (int o = 16; o; o >>= 1) acc += __shfl_xor_sync(0xffffffffu, acc, o);
    if (lane == 0) out[warp] = 1.0f / (1.0f + expf(-(acc + bias[0])));
}

// ---------------- launcher --------------------------------------------------
extern "C" void kernel_launch(void* const* d_in, const int* in_sizes, int n_in,
                              void* d_out, int out_size)
{
    const float* dense_x = (const float*)d_in[0];
    // d_in[1] = lS_o (unused; uniform bags)
    const void*  lS_i    = d_in[2];
    const float* E       = (const float*)d_in[3];
    const float *bW0 = (const float*)d_in[4],  *bb0 = (const float*)d_in[5];
    const float *bW1 = (const float*)d_in[6],  *bb1 = (const float*)d_in[7];
    const float *bW2 = (const float*)d_in[8],  *bb2 = (const float*)d_in[9];
    const float *tW0 = (const float*)d_in[10], *tb0 = (const float*)d_in[11];
    const float *tW1 = (const float*)d_in[12], *tb1 = (const float*)d_in[13];
    const float *tW2 = (const float*)d_in[14], *tb2 = (const float*)d_in[15];
    float* out = (float*)d_out;

    float *x1, *x2, *R, *z1, *z2, *W0p;
    cudaGetSymbolAddress((void**)&x1,  g_x1);
    cudaGetSymbolAddress((void**)&x2,  g_x2);
    cudaGetSymbolAddress((void**)&R,   g_R);
    cudaGetSymbolAddress((void**)&z1,  g_z1);
    cudaGetSymbolAddress((void**)&z2,  g_z2);
    cudaGetSymbolAddress((void**)&W0p, g_W0p);

    // index dtype detection + weight repack (tiny)
    detect_kernel<<<1, 32>>>((const int*)lS_i);
    packw0_kernel<<<(512 * R_W + 255) / 256, 256>>>(tW0, W0p);

    // bottom MLP
    bot0_kernel<<<BATCH / 16, 256>>>(dense_x, bW0, bb0, x1);
    {
        dim3 grid(256 / 128, BATCH / 128);
        gemm_tf32x3<128, true><<<grid, 256>>>(x1, bW1, bb1, x2, BATCH, 256, 512, 256);
    }
    {   // bot layer2 writes straight into R columns 0..63 (ldc = R_W)
        dim3 grid(1, BATCH / 128);
        gemm_tf32x3<64, true><<<grid, 256>>>(x2, bW2, bb2, R, BATCH, 64, 256, R_W);
    }

    // fused embedding gather + interaction -> R cols 64..415 (2 samples/block)
    embed_interact_kernel<<<BATCH / 2, 256>>>(lS_i, E, R);

    // top MLP
    {
        dim3 grid(512 / 128, BATCH / 128);
        gemm_tf32x3<128, true><<<grid, 256>>>(R, W0p, tb0, z1, BATCH, 512, R_W, 512);
    }
    {
        dim3 grid(256 / 128, BATCH / 128);
        gemm_tf32x3<128, true><<<grid, 256>>>(z1, tW1, tb1, z2, BATCH, 256, 512, 256);
    }
    top2_kernel<<<BATCH / 8, 256>>>(z2, tW2, tb2, out);
}

// round 17
// speedup vs baseline: 1.2085x; 1.0704x over previous
#include <cuda_runtime.h>
#include <cuda_bf16.h>
#include <math.h>

// ---------------- problem constants ----------------
#define NUM_TABLES 26
#define N_ROWS 100000
#define EMB_M 64
#define BATCH 16384
#define BAG_L 2
#define NI 27                 // 1 + NUM_TABLES
#define NPAIRS 351            // 27*26/2
#define R_W 416               // 64 + 351 = 415, padded to 416
#define TS_LD 68              // smem row pitch (floats): 16B-aligned, bank-rotating

// ---------------- scratch (static device globals; no cudaMalloc allowed) ----
__device__ float g_x1[BATCH * 512];          // bot layer0 out
__device__ float g_x2[BATCH * 256];          // bot layer1 out
__device__ float g_R [BATCH * R_W];          // [x | pairs | pad]: bot L2 writes cols 0..63
__device__ float g_z1[BATCH * 512];          // top layer0 out
__device__ float g_z2[BATCH * 256];          // top layer1 out
__device__ float g_W0p[512 * R_W];           // top_W0 repacked to stride 416 (zero pad)
__device__ int   g_idx64;                    // 1 if lS_i is int64, 0 if int32

// ---------------- index dtype detection -------------------------------------
__global__ void detect_kernel(const int* __restrict__ p)
{
    if (threadIdx.x == 0) {
        int ok = 1;
        for (int i = 1; i < 128; i += 2) ok &= (p[i] == 0);
        g_idx64 = ok;
    }
}

// ---------------- bottom layer 0: [B,13] -> relu([B,512]) -------------------
__global__ __launch_bounds__(256) void bot0_kernel(
    const float* __restrict__ X, const float* __restrict__ W,
    const float* __restrict__ bias, float* __restrict__ Y)
{
    __shared__ float Ws[512 * 13];
    __shared__ float bs[512];
    __shared__ float Xs[16][13];
    int tid = threadIdx.x;
    for (int i = tid; i < 512 * 13; i += 256) Ws[i] = W[i];
    for (int i = tid; i < 512; i += 256) bs[i] = bias[i];
    int row0 = blockIdx.x * 16;
    for (int i = tid; i < 16 * 13; i += 256)
        Xs[i / 13][i % 13] = X[(long long)(row0 + i / 13) * 13 + (i % 13)];
    __syncthreads();
    for (int r = 0; r < 16; r++) {
        float xr[13];
#pragma unroll
        for (int k = 0; k < 13; k++) xr[k] = Xs[r][k];
#pragma unroll 2
        for (int c = tid; c < 512; c += 256) {
            float acc = bs[c];
#pragma unroll
            for (int k = 0; k < 13; k++) acc = fmaf(xr[k], Ws[c * 13 + k], acc);
            Y[(long long)(row0 + r) * 512 + c] = fmaxf(acc, 0.0f);
        }
    }
}

// ---------------- tf32x3 tensor-core GEMM, double-buffered, BK=16 -----------
// C = act(A[M,K] @ W[N,K]^T + bias), fp32 in/out, hi/lo tf32 split for
// fp32-grade accuracy. BM=128, BK=16, BN in {64,128}, 256 threads, 2 dynamic-
// smem stages, __launch_bounds__(256,2) (R14: occ fix gave 577->511us; tensor
// still 40.7% with 64 barrier windows/K=512 -> this halves barriers and
// doubles the mma run per window to 96). Swizzle col' = m ^ 8*((k&3)^((k>>2)&3))
// is conflict-free for both STS and fragment-LDS patterns (audited in R2).

#define MMA_TF32(d, a, b0, b1)                                              \
    asm volatile("mma.sync.aligned.m16n8k8.row.col.f32.tf32.tf32.f32 "       \
        "{%0,%1,%2,%3}, {%4,%5,%6,%7}, {%8,%9}, {%0,%1,%2,%3};"              \
        : "+f"((d)[0]), "+f"((d)[1]), "+f"((d)[2]), "+f"((d)[3])             \
        : "r"((a)[0]), "r"((a)[1]), "r"((a)[2]), "r"((a)[3]),                \
          "r"(b0), "r"(b1))

template <int WIDTH>
__device__ __forceinline__ void store_split(
    unsigned (*SH)[WIDTH], unsigned (*SL)[WIDTH], int m, int kbase, float4 v)
{
    float f[4] = {v.x, v.y, v.z, v.w};
#pragma unroll
    for (int j = 0; j < 4; j++) {
        int k = kbase + j;
        int cs = (((k & 3) ^ ((k >> 2) & 3)) << 3);
        unsigned hi; asm("cvt.rna.tf32.f32 %0, %1;" : "=r"(hi) : "f"(f[j]));
        float r = f[j] - __uint_as_float(hi);
        unsigned lo; asm("cvt.rna.tf32.f32 %0, %1;" : "=r"(lo) : "f"(r));
        SH[k][m ^ cs] = hi;
        SL[k][m ^ cs] = lo;
    }
}

template <int BN, bool RELU>
__global__ __launch_bounds__(256, 2) void gemm_tf32x3(
    const float* __restrict__ A, const float* __restrict__ W,
    const float* __restrict__ bias, float* __restrict__ C,
    int M, int N, int K, int ldc)
{
    constexpr int BM = 128, BK = 16;
    constexpr int NB  = BN / 64;               // B row-groups per thread (1|2)
    constexpr int WN  = (BN == 128) ? 2 : 1;   // warps along n
    constexpr int WM  = 8 / WN;                // warps along m
    constexpr int WTM = BM / WM;               // 32 or 16
    constexpr int WTN = BN / WN;               // 64
    constexpr int MT  = WTM / 16;              // 2 or 1
    constexpr int NT  = WTN / 8;               // 8

    // dynamic smem: AsH[2][BK][BM] AsL[...] BsH[2][BK][BN] BsL[...]
    extern __shared__ unsigned dsm[];
    typedef unsigned (*TileA)[BK][BM];
    typedef unsigned (*TileB)[BK][BN];
    TileA AsH = (TileA)dsm;
    TileA AsL = (TileA)(dsm + 2 * BK * BM);
    TileB BsH = (TileB)(dsm + 4 * BK * BM);
    TileB BsL = (TileB)(dsm + 4 * BK * BM + 2 * BK * BN);

    int tid = threadIdx.x, lane = tid & 31, warp = tid >> 5;
    int wm = warp % WM, wn = warp / WM;
    int bm = blockIdx.y * BM, bn = blockIdx.x * BN;

    float acc[MT][NT][4];
#pragma unroll
    for (int i = 0; i < MT; i++)
#pragma unroll
        for (int j = 0; j < NT; j++)
#pragma unroll
            for (int t = 0; t < 4; t++) acc[i][j][t] = 0.0f;

    // tile-load mapping: lm = row within 64-row group, lk = 4-k offset
    int lm = tid >> 2;             // 0..63
    int lk = (tid & 3) * 4;        // 0,4,8,12
    const int T_TILES = K / BK;

    const float* Ap = A + (long long)(bm + lm) * K + lk;
    const float* Wp = W + (long long)(bn + lm) * K + lk;

    // prologue: tile 0 -> stage 0, then prefetch tile 1 into regs
    float4 va[2], vb[NB];
#pragma unroll
    for (int h = 0; h < 2; h++)  va[h] = *(const float4*)(Ap + (long long)h * 64 * K);
#pragma unroll
    for (int h = 0; h < NB; h++) vb[h] = *(const float4*)(Wp + (long long)h * 64 * K);
#pragma unroll
    for (int h = 0; h < 2; h++)  store_split<BM>(AsH[0], AsL[0], lm + h * 64, lk, va[h]);
#pragma unroll
    for (int h = 0; h < NB; h++) store_split<BN>(BsH[0], BsL[0], lm + h * 64, lk, vb[h]);
    __syncthreads();
    if (T_TILES > 1) {
#pragma unroll
        for (int h = 0; h < 2; h++)  va[h] = *(const float4*)(Ap + (long long)h * 64 * K + BK);
#pragma unroll
        for (int h = 0; h < NB; h++) vb[h] = *(const float4*)(Wp + (long long)h * 64 * K + BK);
    }

    for (int t = 0; t < T_TILES; t++) {
        int s = t & 1;
        // stage tile t+1 into the other buffer (drains under compute below)
        if (t + 1 < T_TILES) {
#pragma unroll
            for (int h = 0; h < 2; h++)  store_split<BM>(AsH[s ^ 1], AsL[s ^ 1], lm + h * 64, lk, va[h]);
#pragma unroll
            for (int h = 0; h < NB; h++) store_split<BN>(BsH[s ^ 1], BsL[s ^ 1], lm + h * 64, lk, vb[h]);
        }
        // prefetch tile t+2
        if (t + 2 < T_TILES) {
            long long off = (long long)(t + 2) * BK;
#pragma unroll
            for (int h = 0; h < 2; h++)  va[h] = *(const float4*)(Ap + (long long)h * 64 * K + off);
#pragma unroll
            for (int h = 0; h < NB; h++) vb[h] = *(const float4*)(Wp + (long long)h * 64 * K + off);
        }

        // compute stage s: two 8-k-steps (96 mma per warp, one barrier window)
#pragma unroll
        for (int ks = 0; ks < BK; ks += 8) {
            int q = lane & 3, r = lane >> 2;
            int k1 = ks + q, k2 = k1 + 4;
            int c1 = (((k1 & 3) ^ ((k1 >> 2) & 3)) << 3);
            int c2 = (((k2 & 3) ^ ((k2 >> 2) & 3)) << 3);

            unsigned aH[MT][4], aL[MT][4];
#pragma unroll
            for (int mt = 0; mt < MT; mt++) {
                int m0 = wm * WTM + mt * 16 + r;
                aH[mt][0] = AsH[s][k1][m0 ^ c1];       aL[mt][0] = AsL[s][k1][m0 ^ c1];
                aH[mt][1] = AsH[s][k1][(m0 + 8) ^ c1]; aL[mt][1] = AsL[s][k1][(m0 + 8) ^ c1];
                aH[mt][2] = AsH[s][k2][m0 ^ c2];       aL[mt][2] = AsL[s][k2][m0 ^ c2];
                aH[mt][3] = AsH[s][k2][(m0 + 8) ^ c2]; aL[mt][3] = AsL[s][k2][(m0 + 8) ^ c2];
            }
#pragma unroll
            for (int nt = 0; nt < NT; nt++) {
                int n0 = wn * WTN + nt * 8 + r;
                unsigned bH0 = BsH[s][k1][n0 ^ c1], bH1 = BsH[s][k2][n0 ^ c2];
                unsigned bL0 = BsL[s][k1][n0 ^ c1], bL1 = BsL[s][k2][n0 ^ c2];
#pragma unroll
                for (int mt = 0; mt < MT; mt++) {
                    MMA_TF32(acc[mt][nt], aH[mt], bL0, bL1);
                    MMA_TF32(acc[mt][nt], aL[mt], bH0, bH1);
                    MMA_TF32(acc[mt][nt], aH[mt], bH0, bH1);
                }
            }
        }
        __syncthreads();
    }

    // epilogue
    int lane_r = lane >> 2, lane_c = (lane & 3) * 2;
#pragma unroll
    for (int mt = 0; mt < MT; mt++) {
#pragma unroll
        for (int nt = 0; nt < NT; nt++) {
            int row = bm + wm * WTM + mt * 16 + lane_r;
            int col = bn + wn * WTN + nt * 8 + lane_c;
            float bv0 = __ldg(bias + col), bv1 = __ldg(bias + col + 1);
            float v0 = acc[mt][nt][0] + bv0, v1 = acc[mt][nt][1] + bv1;
            float v2 = acc[mt][nt][2] + bv0, v3 = acc[mt][nt][3] + bv1;
            if (RELU) {
                v0 = fmaxf(v0, 0.0f); v1 = fmaxf(v1, 0.0f);
                v2 = fmaxf(v2, 0.0f); v3 = fmaxf(v3, 0.0f);
            }
            *(float2*)(C + (long long)row * ldc + col)       = make_float2(v0, v1);
            *(float2*)(C + (long long)(row + 8) * ldc + col) = make_float2(v2, v3);
        }
    }
}

// dynamic smem sizes (bytes): 2 stages * BK=16 * (BM+BN) * {hi,lo} * 4B
#define GEMM_SMEM(BN) (2 * 16 * (128 + (BN)) * 2 * 4)

// ---------------- fused embedding gather + dot interaction ------------------
__global__ __launch_bounds__(256) void embed_interact_kernel(
    const void* __restrict__ lS_i, const float* __restrict__ E,
    float* __restrict__ R)
{
    __shared__ float Ts2[2][NI * TS_LD];
    __shared__ int   sidx2[2][NUM_TABLES * BAG_L];
    int half = threadIdx.x >> 7;             // 0 or 1: which sample
    int tid  = threadIdx.x & 127;            // lane within the sample's 128 thr
    int b = blockIdx.x * 2 + half;
    float* Ts   = Ts2[half];
    int*   sidx = sidx2[half];
    float* Rb = R + (long long)b * R_W;

    if (tid < NUM_TABLES * BAG_L) {
        int t = tid >> 1, w = tid & 1;
        long long base = (long long)t * (BATCH * BAG_L) + 2LL * b + w;
        sidx[tid] = g_idx64 ? (int)((const long long*)lS_i)[base]
                            : ((const int*)lS_i)[base];
    }
    if (tid < EMB_M / 4)
        *(float4*)(Ts + tid * 4) = *(const float4*)(Rb + tid * 4);
    __syncthreads();

#pragma unroll 2
    for (int i = tid; i < NUM_TABLES * (EMB_M / 4); i += 128) {
        int t = i >> 4, chunk = i & 15;
        long long r0 = (long long)t * N_ROWS + sidx[2 * t];
        long long r1 = (long long)t * N_ROWS + sidx[2 * t + 1];
        float4 a = ((const float4*)(E + r0 * EMB_M))[chunk];
        float4 c = ((const float4*)(E + r1 * EMB_M))[chunk];
        *(float4*)(Ts + (1 + t) * TS_LD + chunk * 4) =
            make_float4(a.x + c.x, a.y + c.y, a.z + c.z, a.w + c.w);
    }
    __syncthreads();

    if (tid == 0) Rb[R_W - 1] = 0.0f;        // zero pad column
    for (int p = tid; p < NPAIRS; p += 128) {
        int i = (int)((1.0f + sqrtf(1.0f + 8.0f * (float)p)) * 0.5f);
        while (i * (i - 1) / 2 > p) i--;
        while ((i + 1) * i / 2 <= p) i++;
        int j = p - i * (i - 1) / 2;
        const float4* ti = (const float4*)(Ts + i * TS_LD);
        const float4* tj = (const float4*)(Ts + j * TS_LD);
        float acc = 0.0f;
#pragma unroll
        for (int k = 0; k < EMB_M / 4; k++) {
            float4 u = ti[k], v = tj[k];
            acc = fmaf(u.x, v.x, acc); acc = fmaf(u.y, v.y, acc);
            acc = fmaf(u.z, v.z, acc); acc = fmaf(u.w, v.w, acc);
        }
        Rb[EMB_M + p] = acc;
    }
}

// ---------------- repack top_W0 [512,415] -> [512,416] with zero pad --------
__global__ void packw0_kernel(const float* __restrict__ W, float* __restrict__ Wp)
{
    int idx = blockIdx.x * blockDim.x + threadIdx.x;
    if (idx >= 512 * R_W) return;
    int n = idx / R_W, k = idx % R_W;
    Wp[idx] = (k < 415) ? W[(long long)n * 415 + k] : 0.0f;
}

// ---------------- top layer 2: [B,256] -> sigmoid([B,1]) --------------------
__global__ __launch_bounds__(256) void top2_kernel(
    const float* __restrict__ Z, const float* __restrict__ W,
    const float* __restrict__ bias, float* __restrict__ out)
{
    __shared__ float Wsm[256];
    int tid = threadIdx.x;
    Wsm[tid] = W[tid];
    __syncthreads();
    int warp = (blockIdx.x * blockDim.x + tid) >> 5;
    int lane = tid & 31;
    if (warp >= BATCH) return;
    const float* z = Z + (long long)warp * 256;
    float acc = 0.0f;
#pragma unroll
    for (int k = lane; k < 256; k += 32) acc = fmaf(z[k], Wsm[k], acc);
#pragma unroll
    for (int o = 16; o; o >>= 1) acc += __shfl_xor_sync(0xffffffffu, acc, o);
    if (lane == 0) out[warp] = 1.0f / (1.0f + expf(-(acc + bias[0])));
}

// ---------------- launcher --------------------------------------------------
extern "C" void kernel_launch(void* const* d_in, const int* in_sizes, int n_in,
                              void* d_out, int out_size)
{
    const float* dense_x = (const float*)d_in[0];
    // d_in[1] = lS_o (unused; uniform bags)
    const void*  lS_i    = d_in[2];
    const float* E       = (const float*)d_in[3];
    const float *bW0 = (const float*)d_in[4],  *bb0 = (const float*)d_in[5];
    const float *bW1 = (const float*)d_in[6],  *bb1 = (const float*)d_in[7];
    const float *bW2 = (const float*)d_in[8],  *bb2 = (const float*)d_in[9];
    const float *tW0 = (const float*)d_in[10], *tb0 = (const float*)d_in[11];
    const float *tW1 = (const float*)d_in[12], *tb1 = (const float*)d_in[13];
    const float *tW2 = (const float*)d_in[14], *tb2 = (const float*)d_in[15];
    float* out = (float*)d_out;

    float *x1, *x2, *R, *z1, *z2, *W0p;
    cudaGetSymbolAddress((void**)&x1,  g_x1);
    cudaGetSymbolAddress((void**)&x2,  g_x2);
    cudaGetSymbolAddress((void**)&R,   g_R);
    cudaGetSymbolAddress((void**)&z1,  g_z1);
    cudaGetSymbolAddress((void**)&z2,  g_z2);
    cudaGetSymbolAddress((void**)&W0p, g_W0p);

    // raise dynamic smem caps (not stream ops; graph-capture-safe, idempotent)
    cudaFuncSetAttribute(gemm_tf32x3<128, true>,
                         cudaFuncAttributeMaxDynamicSharedMemorySize, GEMM_SMEM(128));
    cudaFuncSetAttribute(gemm_tf32x3<64, true>,
                         cudaFuncAttributeMaxDynamicSharedMemorySize, GEMM_SMEM(64));

    // index dtype detection + weight repack (tiny)
    detect_kernel<<<1, 32>>>((const int*)lS_i);
    packw0_kernel<<<(512 * R_W + 255) / 256, 256>>>(tW0, W0p);

    // bottom MLP
    bot0_kernel<<<BATCH / 16, 256>>>(dense_x, bW0, bb0, x1);
    {
        dim3 grid(256 / 128, BATCH / 128);
        gemm_tf32x3<128, true><<<grid, 256, GEMM_SMEM(128)>>>(x1, bW1, bb1, x2, BATCH, 256, 512, 256);
    }
    {   // bot layer2 writes straight into R columns 0..63 (ldc = R_W)
        dim3 grid(1, BATCH / 128);
        gemm_tf32x3<64, true><<<grid, 256, GEMM_SMEM(64)>>>(x2, bW2, bb2, R, BATCH, 64, 256, R_W);
    }

    // fused embedding gather + interaction -> R cols 64..415 (2 samples/block)
    embed_interact_kernel<<<BATCH / 2, 256>>>(lS_i, E, R);

    // top MLP
    {
        dim3 grid(512 / 128, BATCH / 128);
        gemm_tf32x3<128, true><<<grid, 256, GEMM_SMEM(128)>>>(R, W0p, tb0, z1, BATCH, 512, R_W, 512);
    }
    {
        dim3 grid(256 / 128, BATCH / 128);
        gemm_tf32x3<128, true><<<grid, 256, GEMM_SMEM(128)>>>(z1, tW1, tb1, z2, BATCH, 256, 512, 256);
    }
    top2_kernel<<<BATCH / 8, 256>>>(z2, tW2, tb2, out);
}